// round 16
// baseline (speedup 1.0000x reference)
#include <cuda_runtime.h>
#include <cuda_bf16.h>
#include <math.h>
#include <stdint.h>

#define B_ 8
#define N_ 1024
#define M_ 1024
#define D_ 256
#define H_ 4
#define P_ 128
#define C_ 64
#define CP_ 32   // C/2 pairs

// -------- device scratch: bf16x2-packed hi/lo operands (pairs along K dim) --------
__device__ uint32_t g_qh[B_ * H_ * N_ * CP_];
__device__ uint32_t g_ql[B_ * H_ * N_ * CP_];
__device__ uint32_t g_kh[B_ * H_ * M_ * CP_];
__device__ uint32_t g_kl[B_ * H_ * M_ * CP_];
__device__ uint32_t g_vh[B_ * H_ * M_ * CP_];
__device__ uint32_t g_vl[B_ * H_ * M_ * CP_];
__device__ uint32_t g_eh[P_ * D_ / 2];
__device__ uint32_t g_el[P_ * D_ / 2];
__device__ uint32_t g_wsh[3 * D_ * D_ / 2];
__device__ uint32_t g_wsl[3 * D_ * D_ / 2];
__device__ uint32_t g_xh[3 * B_ * N_ * D_ / 2];   // pre-split X (q|k|v inputs)
__device__ uint32_t g_xl[3 * B_ * N_ * D_ / 2];

// ---------------- helpers ----------------
__device__ __forceinline__ void split2(float v0, float v1, uint32_t& hp, uint32_t& lp) {
    asm("cvt.rn.bf16x2.f32 %0, %1, %2;" : "=r"(hp) : "f"(v1), "f"(v0));
    const float h0 = __uint_as_float(hp << 16);
    const float h1 = __uint_as_float(hp & 0xffff0000u);
    asm("cvt.rn.bf16x2.f32 %0, %1, %2;" : "=r"(lp) : "f"(v1 - h1), "f"(v0 - h0));
}

__device__ __forceinline__ void mma16(float d[4], const uint32_t a[4], const uint32_t b[2]) {
    asm volatile(
        "mma.sync.aligned.m16n8k16.row.col.f32.bf16.bf16.f32 "
        "{%0,%1,%2,%3}, {%4,%5,%6,%7}, {%8,%9}, {%0,%1,%2,%3};"
        : "+f"(d[0]), "+f"(d[1]), "+f"(d[2]), "+f"(d[3])
        : "r"(a[0]), "r"(a[1]), "r"(a[2]), "r"(a[3]), "r"(b[0]), "r"(b[1]));
}

__device__ __forceinline__ void ldsm4(uint32_t r[4], uint32_t a) {
    asm volatile("ldmatrix.sync.aligned.m8n8.x4.shared.b16 {%0,%1,%2,%3}, [%4];"
        : "=r"(r[0]), "=r"(r[1]), "=r"(r[2]), "=r"(r[3]) : "r"(a));
}
__device__ __forceinline__ void ldsm4t(uint32_t r[4], uint32_t a) {
    asm volatile("ldmatrix.sync.aligned.m8n8.x4.trans.shared.b16 {%0,%1,%2,%3}, [%4];"
        : "=r"(r[0]), "=r"(r[1]), "=r"(r[2]), "=r"(r[3]) : "r"(a));
}
__device__ __forceinline__ void cpa16(uint32_t dst, const void* src) {
    asm volatile("cp.async.cg.shared.global [%0], [%1], 16;" :: "r"(dst), "l"(src) : "memory");
}
__device__ __forceinline__ void cp_commit() {
    asm volatile("cp.async.commit_group;" ::: "memory");
}
template <int N> __device__ __forceinline__ void cp_wait() {
    asm volatile("cp.async.wait_group %0;" :: "n"(N) : "memory");
}

// ---------------- fused smem layout (32-bit words) ----------------
#define S_STRIDE  1036   // fp32 logits; packed probs: hi [0,512), lo [520,1032)
#define LO_OFF    520
#define KB_STRIDE 36     // staging: 64 rows x 32 words (+4 pad); 4 buffer pairs
#define KH0_OFF   33152
#define KL0_OFF   35456
#define KH1_OFF   37760
#define KL1_OFF   40064
#define KH2_OFF   42368
#define KL2_OFF   44672
#define KH3_OFF   46976
#define KL3_OFF   49280
#define SP_STRIDE 132
#define SP_OFF    51584
#define SMEM_WORDS 55808
#define SMEM_BYTES (SMEM_WORDS * 4)   // 223232 B

// ============================================================================
// Kernel 0a: split W/emb into packed bf16x2 hi/lo pairs (along d).
// ============================================================================
__global__ __launch_bounds__(256) void split_kernel(
    const float* __restrict__ emb, const float* __restrict__ Wq,
    const float* __restrict__ Wk, const float* __restrict__ Wv)
{
    const int i = blockIdx.x * 256 + threadIdx.x;
    float v0, v1;
    uint32_t *oh, *ol;
    int idx;
    if (i < P_ * D_ / 2) {
        v0 = emb[2 * i]; v1 = emb[2 * i + 1]; oh = g_eh; ol = g_el; idx = i;
    } else {
        const int j = i - P_ * D_ / 2;
        const int which = j >> 15;
        const int jj = j & 32767;
        const float* W = (which == 0) ? Wq : (which == 1) ? Wk : Wv;
        v0 = W[2 * jj]; v1 = W[2 * jj + 1]; oh = g_wsh; ol = g_wsl; idx = j;
    }
    uint32_t hp, lp;
    split2(v0, v1, hp, lp);
    oh[idx] = hp;
    ol[idx] = lp;
}

// ============================================================================
// Kernel 0b: split X inputs (q|k|v) into packed bf16x2 hi/lo pairs.
// ============================================================================
__global__ __launch_bounds__(256) void xsplit_kernel(
    const float* __restrict__ Xq, const float* __restrict__ Xk,
    const float* __restrict__ Xv)
{
    const int which = blockIdx.y;
    const float* X = (which == 0) ? Xq : (which == 1) ? Xk : Xv;
    const int i = blockIdx.x * 256 + threadIdx.x;
    const float2 v = ((const float2*)X)[i];
    uint32_t hp, lp;
    split2(v.x, v.y, hp, lp);
    const size_t o = (size_t)which * (B_ * N_ * D_ / 2) + i;
    g_xh[o] = hp;
    g_xl[o] = lp;
}

// ============================================================================
// Kernel 1: QKV projection, split-bf16 m16n8k16 (3-MMA), ldmatrix frags.
// (unchanged from R15)
// ============================================================================
#define PJ_STRIDE 20
__global__ __launch_bounds__(256, 2) void proj_kernel(
    const float* __restrict__ bq, const float* __restrict__ bk,
    const float* __restrict__ bv)
{
    const int which = blockIdx.z;
    const float* bias = (which == 0) ? bq : (which == 1) ? bk : bv;
    uint32_t* outh    = (which == 0) ? g_qh : (which == 1) ? g_kh : g_vh;
    uint32_t* outl    = (which == 0) ? g_ql : (which == 1) ? g_kl : g_vl;
    const uint32_t* wh_base = g_wsh + which * (D_ * D_ / 2);
    const uint32_t* wl_base = g_wsl + which * (D_ * D_ / 2);
    const uint32_t* xh_base = g_xh + (size_t)which * (B_ * N_ * D_ / 2);
    const uint32_t* xl_base = g_xl + (size_t)which * (B_ * N_ * D_ / 2);

    const int r0 = blockIdx.x * 64;
    const int j0 = blockIdx.y * 64;

    __shared__ uint32_t Xh[2][64 * PJ_STRIDE], Xl[2][64 * PJ_STRIDE];
    __shared__ uint32_t Wh[2][64 * PJ_STRIDE], Wl[2][64 * PJ_STRIDE];

    const int tid  = threadIdx.x;
    const int w    = tid >> 5;
    const int lane = tid & 31;
    const int gid  = lane >> 2;
    const int tg   = lane & 3;
    const int wr   = w & 3;
    const int wc   = w >> 2;

    const int srow = tid >> 2;
    const int sc   = tid & 3;

    const int lr = lane & 7;
    const uint32_t offA = (uint32_t)(((wr * 16 + ((lane >> 3) & 1) * 8 + lr) * PJ_STRIDE
                                      + (lane >> 4) * 4) * 4);
    const uint32_t offB = (uint32_t)(((wc * 32 + (lane >> 4) * 8 + lr) * PJ_STRIDE
                                      + ((lane >> 3) & 1) * 4) * 4);
    const uint32_t xh_b = (uint32_t)__cvta_generic_to_shared(Xh);
    const uint32_t xl_b = (uint32_t)__cvta_generic_to_shared(Xl);
    const uint32_t wh_b = (uint32_t)__cvta_generic_to_shared(Wh);
    const uint32_t wl_b = (uint32_t)__cvta_generic_to_shared(Wl);
    const uint32_t BUFB = 64 * PJ_STRIDE * 4;

    uint4 xhp = *(const uint4*)&xh_base[(size_t)(r0 + srow) * (D_ / 2) + sc * 4];
    uint4 xlp = *(const uint4*)&xl_base[(size_t)(r0 + srow) * (D_ / 2) + sc * 4];
    uint4 whp = *(const uint4*)&wh_base[(size_t)(j0 + srow) * (D_ / 2) + sc * 4];
    uint4 wlp = *(const uint4*)&wl_base[(size_t)(j0 + srow) * (D_ / 2) + sc * 4];

    float hh[4][4] = {}, hl[4][4] = {}, lh[4][4] = {};

    for (int mc = 0; mc < 8; mc++) {
        const int bsel = mc & 1;
        {
            *(uint4*)&Xh[bsel][srow * PJ_STRIDE + sc * 4] = xhp;
            *(uint4*)&Xl[bsel][srow * PJ_STRIDE + sc * 4] = xlp;
            *(uint4*)&Wh[bsel][srow * PJ_STRIDE + sc * 4] = whp;
            *(uint4*)&Wl[bsel][srow * PJ_STRIDE + sc * 4] = wlp;
        }
        if (mc < 7) {
            const int kp = (mc + 1) * 16;
            xhp = *(const uint4*)&xh_base[(size_t)(r0 + srow) * (D_ / 2) + kp + sc * 4];
            xlp = *(const uint4*)&xl_base[(size_t)(r0 + srow) * (D_ / 2) + kp + sc * 4];
            whp = *(const uint4*)&wh_base[(size_t)(j0 + srow) * (D_ / 2) + kp + sc * 4];
            wlp = *(const uint4*)&wl_base[(size_t)(j0 + srow) * (D_ / 2) + kp + sc * 4];
        }
        __syncthreads();

        const uint32_t bo = bsel * BUFB;
#pragma unroll
        for (int kb = 0; kb < 2; kb++) {
            uint32_t ah4[4], al4[4];
            ldsm4(ah4, xh_b + bo + offA + kb * 32);
            ldsm4(al4, xl_b + bo + offA + kb * 32);
#pragma unroll
            for (int np = 0; np < 2; np++) {
                uint32_t bh4[4], bl4[4];
                const uint32_t boff = bo + offB + np * (16 * PJ_STRIDE * 4) + kb * 32;
                ldsm4(bh4, wh_b + boff);
                ldsm4(bl4, wl_b + boff);
                mma16(hh[np * 2],     ah4, bh4);
                mma16(hl[np * 2],     ah4, bl4);
                mma16(lh[np * 2],     al4, bh4);
                mma16(hh[np * 2 + 1], ah4, bh4 + 2);
                mma16(hl[np * 2 + 1], ah4, bl4 + 2);
                mma16(lh[np * 2 + 1], al4, bh4 + 2);
            }
        }
    }

#pragma unroll
    for (int ns = 0; ns < 4; ns++) {
        const int col = j0 + wc * 32 + ns * 8 + 2 * tg;
        const float b0 = bias[col], b1 = bias[col + 1];
        const int h = col >> 6, cpair = (col & 63) >> 1;
#pragma unroll
        for (int half = 0; half < 2; half++) {
            const int r = r0 + wr * 16 + gid + half * 8;
            const int bb = r >> 10, l = r & 1023;
            const size_t idx = (((size_t)(bb * H_ + h) * N_) + l) * CP_ + cpair;
            const float v0 = hh[ns][half * 2 + 0] + hl[ns][half * 2 + 0] + lh[ns][half * 2 + 0] + b0;
            const float v1 = hh[ns][half * 2 + 1] + hl[ns][half * 2 + 1] + lh[ns][half * 2 + 1] + b1;
            uint32_t hp, lp;
            split2(v0, v1, hp, lp);
            outh[idx] = hp;
            outl[idx] = lp;
        }
    }
}

// ============================================================================
// Kernel 2: FUSED sp + scores + softmax(+epilogue) + AV.
// 512 threads; cp.async, 2-chunk phases (1 barrier per 2 chunks).
// ============================================================================
__global__ __launch_bounds__(512, 1) void fused_kernel(
    const float* __restrict__ factor, const int* __restrict__ eidx,
    const unsigned char* __restrict__ kmask,
    float* __restrict__ attn, float* __restrict__ hidden)
{
    extern __shared__ float smf[];
    float*    S   = smf;
    uint32_t* Su  = (uint32_t*)smf;
    uint32_t* KH0 = (uint32_t*)(smf + KH0_OFF);
    uint32_t* KL0 = (uint32_t*)(smf + KL0_OFF);
    uint32_t* KH1 = (uint32_t*)(smf + KH1_OFF);
    uint32_t* KL1 = (uint32_t*)(smf + KL1_OFF);
    float*    Sp  = smf + SP_OFF;

    const int tid  = threadIdx.x;
    const int w    = tid >> 5;
    const int lane = tid & 31;
    const int gid  = lane >> 2;
    const int tg   = lane & 3;
    const int wm   = w & 7;
    const int mt   = w >> 3;
    const int bh = blockIdx.y, b = bh >> 2, h = bh & 3;
    const int n0 = blockIdx.x * 32;
    const int r0 = mt * 16 + gid;

    const int kst_r = tid >> 3;
    const int kst_c = (tid & 7) * 4;
    const uint32_t st_off = (uint32_t)((kst_r * KB_STRIDE + kst_c) * 4);

    const uint32_t smem_u = (uint32_t)__cvta_generic_to_shared(smf);
    const int lg = lane >> 3, lr = lane & 7;
    const uint32_t offKB = (uint32_t)(((wm * 8 + lr) * KB_STRIDE + lg * 4) * 4);
    const uint32_t offVB = (uint32_t)(((lg * 8 + lr) * KB_STRIDE + wm * 4) * 4);
    const uint32_t offAh = (uint32_t)(((mt * 16 + (lg & 1) * 8 + lr) * S_STRIDE + (lg >> 1) * 4) * 4);
    const uint32_t KHb[4] = {smem_u + KH0_OFF * 4, smem_u + KH1_OFF * 4,
                             smem_u + KH2_OFF * 4, smem_u + KH3_OFF * 4};
    const uint32_t KLb[4] = {smem_u + KL0_OFF * 4, smem_u + KL1_OFF * 4,
                             smem_u + KL2_OFF * 4, smem_u + KL3_OFF * 4};

    const uint32_t* kh_base = g_kh + (size_t)bh * M_ * CP_;
    const uint32_t* kl_base = g_kl + (size_t)bh * M_ * CP_;
    const uint32_t* vh_base = g_vh + (size_t)bh * M_ * CP_;
    const uint32_t* vl_base = g_vl + (size_t)bh * M_ * CP_;

    // ---------- stage Q (32 rows x 32 pairs) through buffer 0 ----------
    {
        const uint32_t* qh = g_qh + ((size_t)bh * N_ + n0) * CP_;
        const uint32_t* ql = g_ql + ((size_t)bh * N_ + n0) * CP_;
        uint2 q2h = ((const uint2*)qh)[tid];
        uint2 q2l = ((const uint2*)ql)[tid];
        const int qr = tid >> 4, qc = (tid & 15) * 2;
        *(uint2*)&KH0[qr * KB_STRIDE + qc] = q2h;
        *(uint2*)&KL0[qr * KB_STRIDE + qc] = q2l;
    }
    uint4 eph, epl;
    eph = *(const uint4*)&g_eh[(size_t)kst_r * (D_ / 2) + h * CP_ + kst_c];
    epl = *(const uint4*)&g_el[(size_t)kst_r * (D_ / 2) + h * CP_ + kst_c];
    __syncthreads();

    // ---------- preload Q hi+lo fragments (4 k16-blocks) ----------
    uint32_t qfh[4][4], qfl[4][4];
#pragma unroll
    for (int kb = 0; kb < 4; kb++) {
        const int c0 = kb * 8 + tg;
        qfh[kb][0] = KH0[r0 * KB_STRIDE + c0];
        qfh[kb][1] = KH0[(r0 + 8) * KB_STRIDE + c0];
        qfh[kb][2] = KH0[r0 * KB_STRIDE + c0 + 4];
        qfh[kb][3] = KH0[(r0 + 8) * KB_STRIDE + c0 + 4];
        qfl[kb][0] = KL0[r0 * KB_STRIDE + c0];
        qfl[kb][1] = KL0[(r0 + 8) * KB_STRIDE + c0];
        qfl[kb][2] = KL0[r0 * KB_STRIDE + c0 + 4];
        qfl[kb][3] = KL0[(r0 + 8) * KB_STRIDE + c0 + 4];
    }
    __syncthreads();

    // ---------- SP: Sp(32x128) = Q · emb_h^T (2 chunks through bufs 0,1) ----------
#pragma unroll
    for (int pc = 0; pc < 2; pc++) {
        uint32_t* Khw = pc ? KH1 : KH0;
        uint32_t* Klw = pc ? KL1 : KL0;
        *(uint4*)((char*)Khw + st_off) = eph;
        *(uint4*)((char*)Klw + st_off) = epl;
        if (pc == 0) {
            eph = *(const uint4*)&g_eh[(size_t)(64 + kst_r) * (D_ / 2) + h * CP_ + kst_c];
            epl = *(const uint4*)&g_el[(size_t)(64 + kst_r) * (D_ / 2) + h * CP_ + kst_c];
        }
        __syncthreads();

        float hh[4] = {}, hl[4] = {}, lh[4] = {};
#pragma unroll
        for (int kbp = 0; kbp < 2; kbp++) {
            uint32_t bh4[4], bl4[4];
            ldsm4(bh4, KHb[pc] + offKB + kbp * 64);
            ldsm4(bl4, KLb[pc] + offKB + kbp * 64);
            mma16(hh, qfh[2 * kbp], bh4);
            mma16(hl, qfh[2 * kbp], bl4);
            mma16(lh, qfl[2 * kbp], bh4);
            mma16(hh, qfh[2 * kbp + 1], bh4 + 2);
            mma16(hl, qfh[2 * kbp + 1], bl4 + 2);
            mma16(lh, qfl[2 * kbp + 1], bh4 + 2);
        }
        const int col = pc * 64 + wm * 8 + 2 * tg;
        *(float2*)(Sp + r0 * SP_STRIDE + col) =
            make_float2(hh[0] + hl[0] + lh[0], hh[1] + hl[1] + lh[1]);
        *(float2*)(Sp + (r0 + 8) * SP_STRIDE + col) =
            make_float2(hh[2] + hl[2] + lh[2], hh[3] + hl[3] + lh[3]);
    }
    __syncthreads();   // all SP reads done before cp.async overwrites bufs 0,1

    // ---------- GEMM1 prologue: issue phase 0 (chunks 0,1 -> bufs 0,1) ----------
#pragma unroll
    for (int c = 0; c < 2; c++) {
        cpa16(KHb[c] + st_off, kh_base + (size_t)c * 2048 + tid * 4);
        cpa16(KLb[c] + st_off, kl_base + (size_t)c * 2048 + tid * 4);
    }
    cp_commit();

    // ---------- GEMM1: 8 phases x 2 chunks, ONE barrier per phase ----------
    for (int ph = 0; ph < 8; ph++) {
        cp_wait<0>();
        __syncthreads();
        if (ph < 7) {   // issue next phase into the other buffer pair
            const int pb = 2 * ((ph + 1) & 1);
#pragma unroll
            for (int c = 0; c < 2; c++) {
                const size_t mc = (size_t)(2 * (ph + 1) + c);
                cpa16(KHb[pb + c] + st_off, kh_base + mc * 2048 + tid * 4);
                cpa16(KLb[pb + c] + st_off, kl_base + mc * 2048 + tid * 4);
            }
            cp_commit();
        }
        const int pb = 2 * (ph & 1);
#pragma unroll
        for (int c2 = 0; c2 < 2; c2++) {
            const int mc = 2 * ph + c2;
            const int bi = pb + c2;
            float hh[4] = {}, hl[4] = {}, lh[4] = {};
#pragma unroll
            for (int kbp = 0; kbp < 2; kbp++) {
                uint32_t bh4[4], bl4[4];
                ldsm4(bh4, KHb[bi] + offKB + kbp * 64);
                ldsm4(bl4, KLb[bi] + offKB + kbp * 64);
                mma16(hh, qfh[2 * kbp], bh4);
                mma16(hl, qfh[2 * kbp], bl4);
                mma16(lh, qfl[2 * kbp], bh4);
                mma16(hh, qfh[2 * kbp + 1], bh4 + 2);
                mma16(hl, qfh[2 * kbp + 1], bl4 + 2);
                mma16(lh, qfl[2 * kbp + 1], bh4 + 2);
            }
            const int col = mc * 64 + wm * 8 + 2 * tg;
            *(float2*)(S + r0 * S_STRIDE + col) =
                make_float2(hh[0] + hl[0] + lh[0], hh[1] + hl[1] + lh[1]);
            *(float2*)(S + (r0 + 8) * S_STRIDE + col) =
                make_float2(hh[2] + hl[2] + lh[2], hh[3] + hl[3] + lh[3]);
        }
    }
    __syncthreads();   // all GEMM1 reads done; bufs free

    // ---------- AV prologue: issue V phase 0 (overlaps softmax) ----------
#pragma unroll
    for (int c = 0; c < 2; c++) {
        cpa16(KHb[c] + st_off, vh_base + (size_t)c * 2048 + tid * 4);
        cpa16(KLb[c] + st_off, vl_base + (size_t)c * 2048 + tid * 4);
    }
    cp_commit();

    // ---------- softmax with fused epilogue: warp w owns rows 2w, 2w+1 ----------
#pragma unroll
    for (int rr = 0; rr < 2; rr++) {
        const int row = w * 2 + rr;
        const size_t gb = ((size_t)(b * N_ + n0 + row)) * M_;
        const float* sprow = Sp + row * SP_STRIDE;
        float vals[32];
        float mx = -INFINITY;
#pragma unroll
        for (int j = 0; j < 8; j++) {
            const int c4 = (j * 32 + lane) * 4;
            float4 sc = *(float4*)(S + row * S_STRIDE + c4);
            int4   id = *(const int4*)(eidx + gb + c4);
            float4 fa = *(const float4*)(factor + gb + c4);
            const uchar4 km = *(const uchar4*)(kmask + b * M_ + c4);
            float e0 = km.x ? -INFINITY : fa.x * (sc.x + sprow[id.x]) * 0.125f;
            float e1 = km.y ? -INFINITY : fa.y * (sc.y + sprow[id.y]) * 0.125f;
            float e2 = km.z ? -INFINITY : fa.z * (sc.z + sprow[id.z]) * 0.125f;
            float e3 = km.w ? -INFINITY : fa.w * (sc.w + sprow[id.w]) * 0.125f;
            vals[j * 4 + 0] = e0; vals[j * 4 + 1] = e1;
            vals[j * 4 + 2] = e2; vals[j * 4 + 3] = e3;
            mx = fmaxf(mx, fmaxf(fmaxf(e0, e1), fmaxf(e2, e3)));
        }
#pragma unroll
        for (int off = 16; off > 0; off >>= 1)
            mx = fmaxf(mx, __shfl_xor_sync(0xffffffffu, mx, off));
        float sum = 0.f;
#pragma unroll
        for (int i = 0; i < 32; i++) { vals[i] = __expf(vals[i] - mx); sum += vals[i]; }
#pragma unroll
        for (int off = 16; off > 0; off >>= 1)
            sum += __shfl_xor_sync(0xffffffffu, sum, off);
        const float inv = 1.0f / sum;
        const size_t abase = ((size_t)(bh * N_ + n0 + row)) * M_;
#pragma unroll
        for (int j = 0; j < 8; j++) {
            const int c4 = (j * 32 + lane) * 4;
            const float p0 = vals[j * 4 + 0] * inv, p1 = vals[j * 4 + 1] * inv;
            const float p2 = vals[j * 4 + 2] * inv, p3 = vals[j * 4 + 3] * inv;
            *(float4*)(attn + abase + c4) = make_float4(p0, p1, p2, p3);
            uint32_t hp0, lp0, hp1, lp1;
            split2(p0, p1, hp0, lp0);
            split2(p2, p3, hp1, lp1);
            const int c2 = c4 >> 1;
            *(uint2*)(Su + row * S_STRIDE + c2)          = make_uint2(hp0, hp1);
            *(uint2*)(Su + row * S_STRIDE + LO_OFF + c2) = make_uint2(lp0, lp1);
        }
    }

    // ---------- AV: 8 phases x 2 chunks, ONE barrier per phase ----------
    float avhh[4] = {}, avhl[4] = {}, avlh[4] = {};
    for (int ph = 0; ph < 8; ph++) {
        cp_wait<0>();
        __syncthreads();   // phase 0: also orders softmax Su writes before AV reads
        if (ph < 7) {
            const int pb = 2 * ((ph + 1) & 1);
#pragma unroll
            for (int c = 0; c < 2; c++) {
                const size_t kc = (size_t)(2 * (ph + 1) + c);
                cpa16(KHb[pb + c] + st_off, vh_base + kc * 2048 + tid * 4);
                cpa16(KLb[pb + c] + st_off, vl_base + kc * 2048 + tid * 4);
            }
            cp_commit();
        }
        const int pb = 2 * (ph & 1);
#pragma unroll
        for (int c2 = 0; c2 < 2; c2++) {
            const int kc = 2 * ph + c2;
            const int bi = pb + c2;
#pragma unroll
            for (int kbp = 0; kbp < 2; kbp++) {
                uint32_t bh4[4], bl4[4];
                ldsm4t(bh4, KHb[bi] + offVB + kbp * (32 * KB_STRIDE * 4));
                ldsm4t(bl4, KLb[bi] + offVB + kbp * (32 * KB_STRIDE * 4));
#pragma unroll
                for (int kk = 0; kk < 2; kk++) {
                    const int kb = 2 * kbp + kk;
                    const uint32_t cboff = (uint32_t)((kc * 32 + kb * 8) * 4);
                    uint32_t ah4[4], al4[4];
                    ldsm4(ah4, smem_u + offAh + cboff);
                    ldsm4(al4, smem_u + offAh + LO_OFF * 4 + cboff);
                    mma16(avhh, ah4, bh4 + 2 * kk);
                    mma16(avhl, ah4, bl4 + 2 * kk);
                    mma16(avlh, al4, bh4 + 2 * kk);
                }
            }
        }
    }

    // store hidden
    {
        const int row = n0 + r0;
        const int col = h * 64 + wm * 8 + 2 * tg;
        *(float2*)(hidden + ((size_t)b * N_ + row) * D_ + col) =
            make_float2(avhh[0] + avhl[0] + avlh[0], avhh[1] + avhl[1] + avlh[1]);
        *(float2*)(hidden + ((size_t)b * N_ + row + 8) * D_ + col) =
            make_float2(avhh[2] + avhl[2] + avlh[2], avhh[3] + avhl[3] + avlh[3]);
    }
}

// ============================================================================
// Launch
// ============================================================================
extern "C" void kernel_launch(void* const* d_in, const int* in_sizes, int n_in,
                              void* d_out, int out_size)
{
    const float* input_q = (const float*)d_in[0];
    const float* input_k = (const float*)d_in[1];
    const float* input_v = (const float*)d_in[2];
    const float* Wq = (const float*)d_in[3];
    const float* bq = (const float*)d_in[4];
    const float* Wk = (const float*)d_in[5];
    const float* bk = (const float*)d_in[6];
    const float* Wv = (const float*)d_in[7];
    const float* bv = (const float*)d_in[8];
    const float* emb_table = (const float*)d_in[9];
    const float* factor = (const float*)d_in[10];
    const int* eidx = (const int*)d_in[11];
    const unsigned char* kmask = (const unsigned char*)d_in[12];

    float* hidden = (float*)d_out;                          // (B,N,D)
    float* attn   = (float*)d_out + (size_t)B_ * N_ * D_;   // (B,H,N,M)

    static int smem_set = 0;
    if (!smem_set) {
        cudaFuncSetAttribute(fused_kernel,
                             cudaFuncAttributeMaxDynamicSharedMemorySize, SMEM_BYTES);
        smem_set = 1;
    }

    split_kernel<<<(P_ * D_ / 2 + 3 * D_ * D_ / 2) / 256, 256>>>(emb_table, Wq, Wk, Wv);

    xsplit_kernel<<<dim3((B_ * N_ * D_ / 2) / 256, 3), 256>>>(input_q, input_k, input_v);

    proj_kernel<<<dim3((B_ * N_) / 64, D_ / 64, 3), 256>>>(bq, bk, bv);

    fused_kernel<<<dim3(N_ / 32, B_ * H_), 512, SMEM_BYTES>>>(
        factor, eidx, kmask, attn, hidden);
}

// round 17
// speedup vs baseline: 1.0595x; 1.0595x over previous
#include <cuda_runtime.h>
#include <cuda_bf16.h>
#include <math.h>
#include <stdint.h>

#define B_ 8
#define N_ 1024
#define M_ 1024
#define D_ 256
#define H_ 4
#define P_ 128
#define C_ 64
#define CP_ 32   // C/2 pairs

// -------- device scratch: bf16x2-packed hi/lo operands (pairs along K dim) --------
__device__ uint32_t g_qh[B_ * H_ * N_ * CP_];
__device__ uint32_t g_ql[B_ * H_ * N_ * CP_];
__device__ uint32_t g_kh[B_ * H_ * M_ * CP_];
__device__ uint32_t g_kl[B_ * H_ * M_ * CP_];
__device__ uint32_t g_vh[B_ * H_ * M_ * CP_];
__device__ uint32_t g_vl[B_ * H_ * M_ * CP_];
__device__ uint32_t g_eh[P_ * D_ / 2];
__device__ uint32_t g_el[P_ * D_ / 2];
__device__ uint32_t g_wsh[3 * D_ * D_ / 2];
__device__ uint32_t g_wsl[3 * D_ * D_ / 2];
__device__ uint32_t g_xh[3 * B_ * N_ * D_ / 2];   // pre-split X (q|k|v inputs)
__device__ uint32_t g_xl[3 * B_ * N_ * D_ / 2];

// ---------------- helpers ----------------
__device__ __forceinline__ void split2(float v0, float v1, uint32_t& hp, uint32_t& lp) {
    asm("cvt.rn.bf16x2.f32 %0, %1, %2;" : "=r"(hp) : "f"(v1), "f"(v0));
    const float h0 = __uint_as_float(hp << 16);
    const float h1 = __uint_as_float(hp & 0xffff0000u);
    asm("cvt.rn.bf16x2.f32 %0, %1, %2;" : "=r"(lp) : "f"(v1 - h1), "f"(v0 - h0));
}

__device__ __forceinline__ void mma16(float d[4], const uint32_t a[4], const uint32_t b[2]) {
    asm volatile(
        "mma.sync.aligned.m16n8k16.row.col.f32.bf16.bf16.f32 "
        "{%0,%1,%2,%3}, {%4,%5,%6,%7}, {%8,%9}, {%0,%1,%2,%3};"
        : "+f"(d[0]), "+f"(d[1]), "+f"(d[2]), "+f"(d[3])
        : "r"(a[0]), "r"(a[1]), "r"(a[2]), "r"(a[3]), "r"(b[0]), "r"(b[1]));
}

__device__ __forceinline__ void ldsm4(uint32_t r[4], uint32_t a) {
    asm volatile("ldmatrix.sync.aligned.m8n8.x4.shared.b16 {%0,%1,%2,%3}, [%4];"
        : "=r"(r[0]), "=r"(r[1]), "=r"(r[2]), "=r"(r[3]) : "r"(a));
}
__device__ __forceinline__ void ldsm4t(uint32_t r[4], uint32_t a) {
    asm volatile("ldmatrix.sync.aligned.m8n8.x4.trans.shared.b16 {%0,%1,%2,%3}, [%4];"
        : "=r"(r[0]), "=r"(r[1]), "=r"(r[2]), "=r"(r[3]) : "r"(a));
}
__device__ __forceinline__ void cpa16(uint32_t dst, const void* src) {
    asm volatile("cp.async.cg.shared.global [%0], [%1], 16;" :: "r"(dst), "l"(src) : "memory");
}
__device__ __forceinline__ void cp_commit() {
    asm volatile("cp.async.commit_group;" ::: "memory");
}
template <int N> __device__ __forceinline__ void cp_wait() {
    asm volatile("cp.async.wait_group %0;" :: "n"(N) : "memory");
}
// streaming (evict-first) loads/stores for read-once / write-once data
__device__ __forceinline__ float4 ldcs4f(const float* p) {
    float4 v;
    asm volatile("ld.global.cs.v4.f32 {%0,%1,%2,%3}, [%4];"
        : "=f"(v.x), "=f"(v.y), "=f"(v.z), "=f"(v.w) : "l"(p));
    return v;
}
__device__ __forceinline__ int4 ldcs4i(const int* p) {
    int4 v;
    asm volatile("ld.global.cs.v4.s32 {%0,%1,%2,%3}, [%4];"
        : "=r"(v.x), "=r"(v.y), "=r"(v.z), "=r"(v.w) : "l"(p));
    return v;
}
__device__ __forceinline__ void stcs4f(float* p, float4 v) {
    asm volatile("st.global.cs.v4.f32 [%0], {%1,%2,%3,%4};"
        :: "l"(p), "f"(v.x), "f"(v.y), "f"(v.z), "f"(v.w) : "memory");
}

// ---------------- fused smem layout (32-bit words) ----------------
#define S_STRIDE  1036   // fp32 logits; packed probs: hi [0,512), lo [520,1032)
#define LO_OFF    520
#define KB_STRIDE 36     // staging: 64 rows x 32 words (+4 pad); 4 buffer pairs
#define KH0_OFF   33152
#define KL0_OFF   35456
#define KH1_OFF   37760
#define KL1_OFF   40064
#define KH2_OFF   42368
#define KL2_OFF   44672
#define KH3_OFF   46976
#define KL3_OFF   49280
#define SP_STRIDE 132
#define SP_OFF    51584
#define SMEM_WORDS 55808
#define SMEM_BYTES (SMEM_WORDS * 4)   // 223232 B

// ============================================================================
// Kernel 0a: split W/emb into packed bf16x2 hi/lo pairs (along d).
// ============================================================================
__global__ __launch_bounds__(256) void split_kernel(
    const float* __restrict__ emb, const float* __restrict__ Wq,
    const float* __restrict__ Wk, const float* __restrict__ Wv)
{
    const int i = blockIdx.x * 256 + threadIdx.x;
    float v0, v1;
    uint32_t *oh, *ol;
    int idx;
    if (i < P_ * D_ / 2) {
        v0 = emb[2 * i]; v1 = emb[2 * i + 1]; oh = g_eh; ol = g_el; idx = i;
    } else {
        const int j = i - P_ * D_ / 2;
        const int which = j >> 15;
        const int jj = j & 32767;
        const float* W = (which == 0) ? Wq : (which == 1) ? Wk : Wv;
        v0 = W[2 * jj]; v1 = W[2 * jj + 1]; oh = g_wsh; ol = g_wsl; idx = j;
    }
    uint32_t hp, lp;
    split2(v0, v1, hp, lp);
    oh[idx] = hp;
    ol[idx] = lp;
}

// ============================================================================
// Kernel 0b: split X inputs (q|k|v) into packed bf16x2 hi/lo pairs.
// ============================================================================
__global__ __launch_bounds__(256) void xsplit_kernel(
    const float* __restrict__ Xq, const float* __restrict__ Xk,
    const float* __restrict__ Xv)
{
    const int which = blockIdx.y;
    const float* X = (which == 0) ? Xq : (which == 1) ? Xk : Xv;
    const int i = blockIdx.x * 256 + threadIdx.x;
    const float2 v = ((const float2*)X)[i];
    uint32_t hp, lp;
    split2(v.x, v.y, hp, lp);
    const size_t o = (size_t)which * (B_ * N_ * D_ / 2) + i;
    g_xh[o] = hp;
    g_xl[o] = lp;
}

// ============================================================================
// Kernel 1: QKV projection, split-bf16 m16n8k16 (3-MMA), ldmatrix frags.
// (unchanged from R15)
// ============================================================================
#define PJ_STRIDE 20
__global__ __launch_bounds__(256, 2) void proj_kernel(
    const float* __restrict__ bq, const float* __restrict__ bk,
    const float* __restrict__ bv)
{
    const int which = blockIdx.z;
    const float* bias = (which == 0) ? bq : (which == 1) ? bk : bv;
    uint32_t* outh    = (which == 0) ? g_qh : (which == 1) ? g_kh : g_vh;
    uint32_t* outl    = (which == 0) ? g_ql : (which == 1) ? g_kl : g_vl;
    const uint32_t* wh_base = g_wsh + which * (D_ * D_ / 2);
    const uint32_t* wl_base = g_wsl + which * (D_ * D_ / 2);
    const uint32_t* xh_base = g_xh + (size_t)which * (B_ * N_ * D_ / 2);
    const uint32_t* xl_base = g_xl + (size_t)which * (B_ * N_ * D_ / 2);

    const int r0 = blockIdx.x * 64;
    const int j0 = blockIdx.y * 64;

    __shared__ uint32_t Xh[2][64 * PJ_STRIDE], Xl[2][64 * PJ_STRIDE];
    __shared__ uint32_t Wh[2][64 * PJ_STRIDE], Wl[2][64 * PJ_STRIDE];

    const int tid  = threadIdx.x;
    const int w    = tid >> 5;
    const int lane = tid & 31;
    const int gid  = lane >> 2;
    const int tg   = lane & 3;
    const int wr   = w & 3;
    const int wc   = w >> 2;

    const int srow = tid >> 2;
    const int sc   = tid & 3;

    const int lr = lane & 7;
    const uint32_t offA = (uint32_t)(((wr * 16 + ((lane >> 3) & 1) * 8 + lr) * PJ_STRIDE
                                      + (lane >> 4) * 4) * 4);
    const uint32_t offB = (uint32_t)(((wc * 32 + (lane >> 4) * 8 + lr) * PJ_STRIDE
                                      + ((lane >> 3) & 1) * 4) * 4);
    const uint32_t xh_b = (uint32_t)__cvta_generic_to_shared(Xh);
    const uint32_t xl_b = (uint32_t)__cvta_generic_to_shared(Xl);
    const uint32_t wh_b = (uint32_t)__cvta_generic_to_shared(Wh);
    const uint32_t wl_b = (uint32_t)__cvta_generic_to_shared(Wl);
    const uint32_t BUFB = 64 * PJ_STRIDE * 4;

    uint4 xhp = *(const uint4*)&xh_base[(size_t)(r0 + srow) * (D_ / 2) + sc * 4];
    uint4 xlp = *(const uint4*)&xl_base[(size_t)(r0 + srow) * (D_ / 2) + sc * 4];
    uint4 whp = *(const uint4*)&wh_base[(size_t)(j0 + srow) * (D_ / 2) + sc * 4];
    uint4 wlp = *(const uint4*)&wl_base[(size_t)(j0 + srow) * (D_ / 2) + sc * 4];

    float hh[4][4] = {}, hl[4][4] = {}, lh[4][4] = {};

    for (int mc = 0; mc < 8; mc++) {
        const int bsel = mc & 1;
        {
            *(uint4*)&Xh[bsel][srow * PJ_STRIDE + sc * 4] = xhp;
            *(uint4*)&Xl[bsel][srow * PJ_STRIDE + sc * 4] = xlp;
            *(uint4*)&Wh[bsel][srow * PJ_STRIDE + sc * 4] = whp;
            *(uint4*)&Wl[bsel][srow * PJ_STRIDE + sc * 4] = wlp;
        }
        if (mc < 7) {
            const int kp = (mc + 1) * 16;
            xhp = *(const uint4*)&xh_base[(size_t)(r0 + srow) * (D_ / 2) + kp + sc * 4];
            xlp = *(const uint4*)&xl_base[(size_t)(r0 + srow) * (D_ / 2) + kp + sc * 4];
            whp = *(const uint4*)&wh_base[(size_t)(j0 + srow) * (D_ / 2) + kp + sc * 4];
            wlp = *(const uint4*)&wl_base[(size_t)(j0 + srow) * (D_ / 2) + kp + sc * 4];
        }
        __syncthreads();

        const uint32_t bo = bsel * BUFB;
#pragma unroll
        for (int kb = 0; kb < 2; kb++) {
            uint32_t ah4[4], al4[4];
            ldsm4(ah4, xh_b + bo + offA + kb * 32);
            ldsm4(al4, xl_b + bo + offA + kb * 32);
#pragma unroll
            for (int np = 0; np < 2; np++) {
                uint32_t bh4[4], bl4[4];
                const uint32_t boff = bo + offB + np * (16 * PJ_STRIDE * 4) + kb * 32;
                ldsm4(bh4, wh_b + boff);
                ldsm4(bl4, wl_b + boff);
                mma16(hh[np * 2],     ah4, bh4);
                mma16(hl[np * 2],     ah4, bl4);
                mma16(lh[np * 2],     al4, bh4);
                mma16(hh[np * 2 + 1], ah4, bh4 + 2);
                mma16(hl[np * 2 + 1], ah4, bl4 + 2);
                mma16(lh[np * 2 + 1], al4, bh4 + 2);
            }
        }
    }

#pragma unroll
    for (int ns = 0; ns < 4; ns++) {
        const int col = j0 + wc * 32 + ns * 8 + 2 * tg;
        const float b0 = bias[col], b1 = bias[col + 1];
        const int h = col >> 6, cpair = (col & 63) >> 1;
#pragma unroll
        for (int half = 0; half < 2; half++) {
            const int r = r0 + wr * 16 + gid + half * 8;
            const int bb = r >> 10, l = r & 1023;
            const size_t idx = (((size_t)(bb * H_ + h) * N_) + l) * CP_ + cpair;
            const float v0 = hh[ns][half * 2 + 0] + hl[ns][half * 2 + 0] + lh[ns][half * 2 + 0] + b0;
            const float v1 = hh[ns][half * 2 + 1] + hl[ns][half * 2 + 1] + lh[ns][half * 2 + 1] + b1;
            uint32_t hp, lp;
            split2(v0, v1, hp, lp);
            outh[idx] = hp;
            outl[idx] = lp;
        }
    }
}

// ============================================================================
// Kernel 2: FUSED sp + scores + softmax(+epilogue) + AV.  (R13 structure)
// 512 threads; cp.async 4-buffer ring (wait<2>); streaming cache hints on
// read-once factor/eidx and write-once attn.
// ============================================================================
__global__ __launch_bounds__(512, 1) void fused_kernel(
    const float* __restrict__ factor, const int* __restrict__ eidx,
    const unsigned char* __restrict__ kmask,
    float* __restrict__ attn, float* __restrict__ hidden)
{
    extern __shared__ float smf[];
    float*    S   = smf;
    uint32_t* Su  = (uint32_t*)smf;
    uint32_t* KH0 = (uint32_t*)(smf + KH0_OFF);
    uint32_t* KL0 = (uint32_t*)(smf + KL0_OFF);
    uint32_t* KH1 = (uint32_t*)(smf + KH1_OFF);
    uint32_t* KL1 = (uint32_t*)(smf + KL1_OFF);
    float*    Sp  = smf + SP_OFF;

    const int tid  = threadIdx.x;
    const int w    = tid >> 5;
    const int lane = tid & 31;
    const int gid  = lane >> 2;
    const int tg   = lane & 3;
    const int wm   = w & 7;
    const int mt   = w >> 3;
    const int bh = blockIdx.y, b = bh >> 2, h = bh & 3;
    const int n0 = blockIdx.x * 32;
    const int r0 = mt * 16 + gid;

    const int kst_r = tid >> 3;
    const int kst_c = (tid & 7) * 4;
    const uint32_t st_off = (uint32_t)((kst_r * KB_STRIDE + kst_c) * 4);

    const uint32_t smem_u = (uint32_t)__cvta_generic_to_shared(smf);
    const int lg = lane >> 3, lr = lane & 7;
    const uint32_t offKB = (uint32_t)(((wm * 8 + lr) * KB_STRIDE + lg * 4) * 4);
    const uint32_t offVB = (uint32_t)(((lg * 8 + lr) * KB_STRIDE + wm * 4) * 4);
    const uint32_t offAh = (uint32_t)(((mt * 16 + (lg & 1) * 8 + lr) * S_STRIDE + (lg >> 1) * 4) * 4);
    const uint32_t KHb[4] = {smem_u + KH0_OFF * 4, smem_u + KH1_OFF * 4,
                             smem_u + KH2_OFF * 4, smem_u + KH3_OFF * 4};
    const uint32_t KLb[4] = {smem_u + KL0_OFF * 4, smem_u + KL1_OFF * 4,
                             smem_u + KL2_OFF * 4, smem_u + KL3_OFF * 4};

    const uint32_t* kh_base = g_kh + (size_t)bh * M_ * CP_;
    const uint32_t* kl_base = g_kl + (size_t)bh * M_ * CP_;
    const uint32_t* vh_base = g_vh + (size_t)bh * M_ * CP_;
    const uint32_t* vl_base = g_vl + (size_t)bh * M_ * CP_;

    // ---------- stage Q (32 rows x 32 pairs) through buffer 0 ----------
    {
        const uint32_t* qh = g_qh + ((size_t)bh * N_ + n0) * CP_;
        const uint32_t* ql = g_ql + ((size_t)bh * N_ + n0) * CP_;
        uint2 q2h = ((const uint2*)qh)[tid];
        uint2 q2l = ((const uint2*)ql)[tid];
        const int qr = tid >> 4, qc = (tid & 15) * 2;
        *(uint2*)&KH0[qr * KB_STRIDE + qc] = q2h;
        *(uint2*)&KL0[qr * KB_STRIDE + qc] = q2l;
    }
    uint4 eph, epl;
    eph = *(const uint4*)&g_eh[(size_t)kst_r * (D_ / 2) + h * CP_ + kst_c];
    epl = *(const uint4*)&g_el[(size_t)kst_r * (D_ / 2) + h * CP_ + kst_c];
    __syncthreads();

    // ---------- preload Q hi+lo fragments (4 k16-blocks) ----------
    uint32_t qfh[4][4], qfl[4][4];
#pragma unroll
    for (int kb = 0; kb < 4; kb++) {
        const int c0 = kb * 8 + tg;
        qfh[kb][0] = KH0[r0 * KB_STRIDE + c0];
        qfh[kb][1] = KH0[(r0 + 8) * KB_STRIDE + c0];
        qfh[kb][2] = KH0[r0 * KB_STRIDE + c0 + 4];
        qfh[kb][3] = KH0[(r0 + 8) * KB_STRIDE + c0 + 4];
        qfl[kb][0] = KL0[r0 * KB_STRIDE + c0];
        qfl[kb][1] = KL0[(r0 + 8) * KB_STRIDE + c0];
        qfl[kb][2] = KL0[r0 * KB_STRIDE + c0 + 4];
        qfl[kb][3] = KL0[(r0 + 8) * KB_STRIDE + c0 + 4];
    }
    __syncthreads();

    // ---------- SP: Sp(32x128) = Q · emb_h^T (2 chunks through bufs 0,1) ----------
#pragma unroll
    for (int pc = 0; pc < 2; pc++) {
        uint32_t* Khw = pc ? KH1 : KH0;
        uint32_t* Klw = pc ? KL1 : KL0;
        *(uint4*)((char*)Khw + st_off) = eph;
        *(uint4*)((char*)Klw + st_off) = epl;
        if (pc == 0) {
            eph = *(const uint4*)&g_eh[(size_t)(64 + kst_r) * (D_ / 2) + h * CP_ + kst_c];
            epl = *(const uint4*)&g_el[(size_t)(64 + kst_r) * (D_ / 2) + h * CP_ + kst_c];
        }
        __syncthreads();

        float hh[4] = {}, hl[4] = {}, lh[4] = {};
#pragma unroll
        for (int kbp = 0; kbp < 2; kbp++) {
            uint32_t bh4[4], bl4[4];
            ldsm4(bh4, KHb[pc] + offKB + kbp * 64);
            ldsm4(bl4, KLb[pc] + offKB + kbp * 64);
            mma16(hh, qfh[2 * kbp], bh4);
            mma16(hl, qfh[2 * kbp], bl4);
            mma16(lh, qfl[2 * kbp], bh4);
            mma16(hh, qfh[2 * kbp + 1], bh4 + 2);
            mma16(hl, qfh[2 * kbp + 1], bl4 + 2);
            mma16(lh, qfl[2 * kbp + 1], bh4 + 2);
        }
        const int col = pc * 64 + wm * 8 + 2 * tg;
        *(float2*)(Sp + r0 * SP_STRIDE + col) =
            make_float2(hh[0] + hl[0] + lh[0], hh[1] + hl[1] + lh[1]);
        *(float2*)(Sp + (r0 + 8) * SP_STRIDE + col) =
            make_float2(hh[2] + hl[2] + lh[2], hh[3] + hl[3] + lh[3]);
    }
    __syncthreads();   // all SP reads done before cp.async overwrites bufs 0,1

    // ---------- GEMM1 prologue: issue K chunks 0..2 into bufs 0..2 ----------
#pragma unroll
    for (int p = 0; p < 3; p++) {
        cpa16(KHb[p] + st_off, kh_base + (size_t)p * 2048 + tid * 4);
        cpa16(KLb[p] + st_off, kl_base + (size_t)p * 2048 + tid * 4);
        cp_commit();
    }

    // ---------- GEMM1: S(32x1024) = Q · K^T (16 chunks, 4-buffer ring) ----------
    for (int mc = 0; mc < 16; mc++) {
        cp_wait<2>();
        __syncthreads();
        if (mc + 3 < 16) {
            const int bi = (mc + 3) & 3;
            cpa16(KHb[bi] + st_off, kh_base + (size_t)(mc + 3) * 2048 + tid * 4);
            cpa16(KLb[bi] + st_off, kl_base + (size_t)(mc + 3) * 2048 + tid * 4);
        }
        cp_commit();

        const int bi = mc & 3;
        float hh[4] = {}, hl[4] = {}, lh[4] = {};
#pragma unroll
        for (int kbp = 0; kbp < 2; kbp++) {
            uint32_t bh4[4], bl4[4];
            ldsm4(bh4, KHb[bi] + offKB + kbp * 64);
            ldsm4(bl4, KLb[bi] + offKB + kbp * 64);
            mma16(hh, qfh[2 * kbp], bh4);
            mma16(hl, qfh[2 * kbp], bl4);
            mma16(lh, qfl[2 * kbp], bh4);
            mma16(hh, qfh[2 * kbp + 1], bh4 + 2);
            mma16(hl, qfh[2 * kbp + 1], bl4 + 2);
            mma16(lh, qfl[2 * kbp + 1], bh4 + 2);
        }
        const int col = mc * 64 + wm * 8 + 2 * tg;
        *(float2*)(S + r0 * S_STRIDE + col) =
            make_float2(hh[0] + hl[0] + lh[0], hh[1] + hl[1] + lh[1]);
        *(float2*)(S + (r0 + 8) * S_STRIDE + col) =
            make_float2(hh[2] + hl[2] + lh[2], hh[3] + hl[3] + lh[3]);
    }
    __syncthreads();

    // ---------- AV prologue: issue V chunks 0..2 (loads overlap softmax) ----------
#pragma unroll
    for (int p = 0; p < 3; p++) {
        cpa16(KHb[p] + st_off, vh_base + (size_t)p * 2048 + tid * 4);
        cpa16(KLb[p] + st_off, vl_base + (size_t)p * 2048 + tid * 4);
        cp_commit();
    }

    // ---------- softmax with fused epilogue: warp w owns rows 2w, 2w+1 ----------
#pragma unroll
    for (int rr = 0; rr < 2; rr++) {
        const int row = w * 2 + rr;
        const size_t gb = ((size_t)(b * N_ + n0 + row)) * M_;
        const float* sprow = Sp + row * SP_STRIDE;
        float vals[32];
        float mx = -INFINITY;
#pragma unroll
        for (int j = 0; j < 8; j++) {
            const int c4 = (j * 32 + lane) * 4;
            float4 sc = *(float4*)(S + row * S_STRIDE + c4);
            int4   id = ldcs4i(eidx + gb + c4);
            float4 fa = ldcs4f(factor + gb + c4);
            const uchar4 km = *(const uchar4*)(kmask + b * M_ + c4);
            float e0 = km.x ? -INFINITY : fa.x * (sc.x + sprow[id.x]) * 0.125f;
            float e1 = km.y ? -INFINITY : fa.y * (sc.y + sprow[id.y]) * 0.125f;
            float e2 = km.z ? -INFINITY : fa.z * (sc.z + sprow[id.z]) * 0.125f;
            float e3 = km.w ? -INFINITY : fa.w * (sc.w + sprow[id.w]) * 0.125f;
            vals[j * 4 + 0] = e0; vals[j * 4 + 1] = e1;
            vals[j * 4 + 2] = e2; vals[j * 4 + 3] = e3;
            mx = fmaxf(mx, fmaxf(fmaxf(e0, e1), fmaxf(e2, e3)));
        }
#pragma unroll
        for (int off = 16; off > 0; off >>= 1)
            mx = fmaxf(mx, __shfl_xor_sync(0xffffffffu, mx, off));
        float sum = 0.f;
#pragma unroll
        for (int i = 0; i < 32; i++) { vals[i] = __expf(vals[i] - mx); sum += vals[i]; }
#pragma unroll
        for (int off = 16; off > 0; off >>= 1)
            sum += __shfl_xor_sync(0xffffffffu, sum, off);
        const float inv = 1.0f / sum;
        const size_t abase = ((size_t)(bh * N_ + n0 + row)) * M_;
#pragma unroll
        for (int j = 0; j < 8; j++) {
            const int c4 = (j * 32 + lane) * 4;
            const float p0 = vals[j * 4 + 0] * inv, p1 = vals[j * 4 + 1] * inv;
            const float p2 = vals[j * 4 + 2] * inv, p3 = vals[j * 4 + 3] * inv;
            stcs4f(attn + abase + c4, make_float4(p0, p1, p2, p3));
            uint32_t hp0, lp0, hp1, lp1;
            split2(p0, p1, hp0, lp0);
            split2(p2, p3, hp1, lp1);
            const int c2 = c4 >> 1;
            *(uint2*)(Su + row * S_STRIDE + c2)          = make_uint2(hp0, hp1);
            *(uint2*)(Su + row * S_STRIDE + LO_OFF + c2) = make_uint2(lp0, lp1);
        }
    }

    // ---------- AV: hidden(32x64) = P · V (16 chunks, 4-buffer ring) ----------
    float avhh[4] = {}, avhl[4] = {}, avlh[4] = {};
    for (int kc = 0; kc < 16; kc++) {
        cp_wait<2>();
        __syncthreads();
        if (kc + 3 < 16) {
            const int bi = (kc + 3) & 3;
            cpa16(KHb[bi] + st_off, vh_base + (size_t)(kc + 3) * 2048 + tid * 4);
            cpa16(KLb[bi] + st_off, vl_base + (size_t)(kc + 3) * 2048 + tid * 4);
        }
        cp_commit();

        const int bi = kc & 3;
#pragma unroll
        for (int kbp = 0; kbp < 2; kbp++) {
            uint32_t bh4[4], bl4[4];
            ldsm4t(bh4, KHb[bi] + offVB + kbp * (32 * KB_STRIDE * 4));
            ldsm4t(bl4, KLb[bi] + offVB + kbp * (32 * KB_STRIDE * 4));
#pragma unroll
            for (int kk = 0; kk < 2; kk++) {
                const int kb = 2 * kbp + kk;
                const uint32_t cboff = (uint32_t)((kc * 32 + kb * 8) * 4);
                uint32_t ah4[4], al4[4];
                ldsm4(ah4, smem_u + offAh + cboff);
                ldsm4(al4, smem_u + offAh + LO_OFF * 4 + cboff);
                mma16(avhh, ah4, bh4 + 2 * kk);
                mma16(avhl, ah4, bl4 + 2 * kk);
                mma16(avlh, al4, bh4 + 2 * kk);
            }
        }
    }

    // store hidden
    {
        const int row = n0 + r0;
        const int col = h * 64 + wm * 8 + 2 * tg;
        *(float2*)(hidden + ((size_t)b * N_ + row) * D_ + col) =
            make_float2(avhh[0] + avhl[0] + avlh[0], avhh[1] + avhl[1] + avlh[1]);
        *(float2*)(hidden + ((size_t)b * N_ + row + 8) * D_ + col) =
            make_float2(avhh[2] + avhl[2] + avlh[2], avhh[3] + avhl[3] + avlh[3]);
    }
}

// ============================================================================
// Launch
// ============================================================================
extern "C" void kernel_launch(void* const* d_in, const int* in_sizes, int n_in,
                              void* d_out, int out_size)
{
    const float* input_q = (const float*)d_in[0];
    const float* input_k = (const float*)d_in[1];
    const float* input_v = (const float*)d_in[2];
    const float* Wq = (const float*)d_in[3];
    const float* bq = (const float*)d_in[4];
    const float* Wk = (const float*)d_in[5];
    const float* bk = (const float*)d_in[6];
    const float* Wv = (const float*)d_in[7];
    const float* bv = (const float*)d_in[8];
    const float* emb_table = (const float*)d_in[9];
    const float* factor = (const float*)d_in[10];
    const int* eidx = (const int*)d_in[11];
    const unsigned char* kmask = (const unsigned char*)d_in[12];

    float* hidden = (float*)d_out;                          // (B,N,D)
    float* attn   = (float*)d_out + (size_t)B_ * N_ * D_;   // (B,H,N,M)

    static int smem_set = 0;
    if (!smem_set) {
        cudaFuncSetAttribute(fused_kernel,
                             cudaFuncAttributeMaxDynamicSharedMemorySize, SMEM_BYTES);
        smem_set = 1;
    }

    split_kernel<<<(P_ * D_ / 2 + 3 * D_ * D_ / 2) / 256, 256>>>(emb_table, Wq, Wk, Wv);

    xsplit_kernel<<<dim3((B_ * N_ * D_ / 2) / 256, 3), 256>>>(input_q, input_k, input_v);

    proj_kernel<<<dim3((B_ * N_) / 64, D_ / 64, 3), 256>>>(bq, bk, bv);

    fused_kernel<<<dim3(N_ / 32, B_ * H_), 512, SMEM_BYTES>>>(
        factor, eidx, kmask, attn, hidden);
}